// round 4
// baseline (speedup 1.0000x reference)
#include <cuda_runtime.h>
#include <cuda_bf16.h>
#include <cstdint>

#define D 128
#define MAXN 40000

// ------------------------- device scratch (no allocs) -----------------------
__device__ __align__(16) float g_AB[(size_t)MAXN * 256]; // [N][256]: 0..127 A=nf@W1^T, 128..255 B'=nf@W2^T+b_e
__device__ __align__(16) float g_agg[(size_t)MAXN * D];  // segment-sum of e over dst
__device__ __align__(16) float g_deg[MAXN];
__device__ __align__(16) __nv_bfloat16 g_We_hi[128 * 384];
__device__ __align__(16) __nv_bfloat16 g_We_lo[128 * 384];
__device__ __align__(16) __nv_bfloat16 g_Wn_hi[128 * 256];
__device__ __align__(16) __nv_bfloat16 g_Wn_lo[128 * 256];

// ------------------------- smem layout --------------------------------------
#define ROWB 272              // bytes per tile row (136 bf16); 272/4=68 words -> 4-bank shift/row
#define A_HI 0
#define A_LO 34816
#define B_HI 69632
#define B_LO 104448
#define IDX_OFF 139264
#define SMEM_BYTES 140288

__device__ __forceinline__ uint32_t smem_u32(const void* p) {
    uint32_t a;
    asm("{ .reg .u64 t; cvta.to.shared.u64 t, %1; cvt.u32.u64 %0, t; }" : "=r"(a) : "l"(p));
    return a;
}

#define LDM4(r, addr) \
    asm volatile("ldmatrix.sync.aligned.m8n8.x4.shared.b16 {%0,%1,%2,%3}, [%4];" \
        : "=r"((r)[0]), "=r"((r)[1]), "=r"((r)[2]), "=r"((r)[3]) : "r"(addr))

__device__ __forceinline__ void mma16816(float* c, const uint32_t* a, const uint32_t* b) {
    asm volatile("mma.sync.aligned.m16n8k16.row.col.f32.bf16.bf16.f32 "
        "{%0,%1,%2,%3}, {%4,%5,%6,%7}, {%8,%9}, {%0,%1,%2,%3};"
        : "+f"(c[0]), "+f"(c[1]), "+f"(c[2]), "+f"(c[3])
        : "r"(a[0]), "r"(a[1]), "r"(a[2]), "r"(a[3]), "r"(b[0]), "r"(b[1]));
}

__device__ __forceinline__ void split2(float x, float y, uint32_t& h, uint32_t& l) {
    __nv_bfloat162 hh = __floats2bfloat162_rn(x, y);
    __nv_bfloat162 ll = __floats2bfloat162_rn(x - __bfloat162float(hh.x),
                                              y - __bfloat162float(hh.y));
    h = *reinterpret_cast<uint32_t*>(&hh);
    l = *reinterpret_cast<uint32_t*>(&ll);
}

// A tile: 128 rows x 128 k fp32 -> bf16 hi/lo into padded smem
__device__ __forceinline__ void fill_A(char* base, const float* __restrict__ g,
                                       int row0, int nrows, const float* __restrict__ deg,
                                       int tid) {
    #pragma unroll
    for (int h = 0; h < 2; ++h) {
        int row = h * 64 + (tid >> 2);
        int q = tid & 3;
        if (row < nrows) {
            float s = 1.f;
            if (deg) s = 1.f / fmaxf(deg[row0 + row], 1.f);
            const float* gr = g + (size_t)(row0 + row) * D + q * 32;
            char* ph = base + A_HI + row * ROWB + q * 64;
            char* pl = base + A_LO + row * ROWB + q * 64;
            #pragma unroll
            for (int j = 0; j < 4; ++j) {
                float4 f0 = *reinterpret_cast<const float4*>(gr + j * 8);
                float4 f1 = *reinterpret_cast<const float4*>(gr + j * 8 + 4);
                f0.x *= s; f0.y *= s; f0.z *= s; f0.w *= s;
                f1.x *= s; f1.y *= s; f1.z *= s; f1.w *= s;
                uint4 H, L;
                split2(f0.x, f0.y, H.x, L.x);
                split2(f0.z, f0.w, H.y, L.y);
                split2(f1.x, f1.y, H.z, L.z);
                split2(f1.z, f1.w, H.w, L.w);
                *reinterpret_cast<uint4*>(ph + j * 16) = H;
                *reinterpret_cast<uint4*>(pl + j * 16) = L;
            }
        }
    }
}

// B tile: 128 n x 128 k from pre-split bf16 weights (row-major n x ldk)
__device__ __forceinline__ void fill_B(char* base,
                                       const __nv_bfloat16* __restrict__ Whi,
                                       const __nv_bfloat16* __restrict__ Wlo,
                                       int k0, int ldk, int tid) {
    int n = tid >> 1, h = tid & 1;
    const __nv_bfloat16* ph = Whi + (size_t)n * ldk + k0 + h * 64;
    const __nv_bfloat16* pl = Wlo + (size_t)n * ldk + k0 + h * 64;
    char* dh = base + B_HI + n * ROWB + h * 128;
    char* dl = base + B_LO + n * ROWB + h * 128;
    #pragma unroll
    for (int j = 0; j < 8; ++j) {
        *reinterpret_cast<uint4*>(dh + j * 16) = *reinterpret_cast<const uint4*>(ph + j * 8);
        *reinterpret_cast<uint4*>(dl + j * 16) = *reinterpret_cast<const uint4*>(pl + j * 8);
    }
}

// 3-pass (hi*hi + hi*lo + lo*hi) 128x128x128 MMA, acc in registers
__device__ __forceinline__ void run_mma(uint32_t sb, int lane, int warpm, int warpn,
                                        float acc[2][8][4]) {
    #pragma unroll
    for (int pass = 0; pass < 3; ++pass) {
        uint32_t aoff = (pass == 2) ? A_LO : A_HI;
        uint32_t boff = (pass == 1) ? B_LO : B_HI;
        uint32_t abase = sb + aoff + (warpm * 32 + (lane & 15)) * ROWB + (lane >> 4) * 16;
        int g = lane >> 3;
        uint32_t bbase = sb + boff + (warpn * 64 + (g >> 1) * 8 + (lane & 7)) * ROWB + (g & 1) * 16;
        #pragma unroll
        for (int k = 0; k < 8; ++k) {
            uint32_t a0[4], a1[4], b[4][4];
            LDM4(a0, abase + k * 32);
            LDM4(a1, abase + 16 * ROWB + k * 32);
            #pragma unroll
            for (int p = 0; p < 4; ++p) LDM4(b[p], bbase + p * 16 * ROWB + k * 32);
            #pragma unroll
            for (int p = 0; p < 4; ++p) {
                mma16816(acc[0][2 * p],     a0, &b[p][0]);
                mma16816(acc[0][2 * p + 1], a0, &b[p][2]);
                mma16816(acc[1][2 * p],     a1, &b[p][0]);
                mma16816(acc[1][2 * p + 1], a1, &b[p][2]);
            }
        }
    }
}

// ------------------------- tiny kernels -------------------------------------
__global__ void k_zero(int n_nodes) {
    int i = blockIdx.x * blockDim.x + threadIdx.x;
    int tot4 = n_nodes * (D / 4);
    if (i < tot4) reinterpret_cast<float4*>(g_agg)[i] = make_float4(0.f, 0.f, 0.f, 0.f);
    if (i < n_nodes) g_deg[i] = 0.f;
}

__global__ void k_wprep(const float* __restrict__ We, const float* __restrict__ Wn) {
    int i = blockIdx.x * blockDim.x + threadIdx.x;
    if (i < 128 * 384) {
        float w = We[i];
        __nv_bfloat16 h = __float2bfloat16(w);
        g_We_hi[i] = h;
        g_We_lo[i] = __float2bfloat16(w - __bfloat162float(h));
    }
    if (i < 128 * 256) {
        float w = Wn[i];
        __nv_bfloat16 h = __float2bfloat16(w);
        g_Wn_hi[i] = h;
        g_Wn_lo[i] = __float2bfloat16(w - __bfloat162float(h));
    }
}

// ------------------------- main kernels -------------------------------------
// k_pre: g_AB[m][half*128 + c] = nf@We[:,half*128:...]^T (+ b_e for half 1)
__global__ void __launch_bounds__(256, 1)
k_pre(const float* __restrict__ nf, const float* __restrict__ b_e, int N) {
    extern __shared__ char smem[];
    uint32_t sb = smem_u32(smem);
    int tid = threadIdx.x, lane = tid & 31, warp = tid >> 5;
    int warpm = warp & 3, warpn = warp >> 2;
    int mbase = blockIdx.x * 128, half = blockIdx.y;
    int nrows = min(128, N - mbase);

    fill_A(smem, nf, mbase, nrows, nullptr, tid);
    fill_B(smem, g_We_hi, g_We_lo, half * 128, 384, tid);
    __syncthreads();

    float acc[2][8][4];
    #pragma unroll
    for (int i = 0; i < 2; ++i)
        #pragma unroll
        for (int j = 0; j < 8; ++j)
            #pragma unroll
            for (int k = 0; k < 4; ++k) acc[i][j][k] = 0.f;
    run_mma(sb, lane, warpm, warpn, acc);

    int q = lane & 3, r4 = lane >> 2;
    #pragma unroll
    for (int mt = 0; mt < 2; ++mt)
        #pragma unroll
        for (int rh = 0; rh < 2; ++rh) {
            int rl = warpm * 32 + mt * 16 + rh * 8 + r4;
            int m = mbase + rl;
            if (m < N) {
                float* pd = g_AB + (size_t)m * 256 + half * 128;
                #pragma unroll
                for (int nt = 0; nt < 8; ++nt) {
                    int col = warpn * 64 + nt * 8 + q * 2;
                    float vx = acc[mt][nt][rh * 2 + 0];
                    float vy = acc[mt][nt][rh * 2 + 1];
                    if (half == 1) {
                        float2 bb = *reinterpret_cast<const float2*>(b_e + col);
                        vx += bb.x; vy += bb.y;
                    }
                    *reinterpret_cast<float2*>(pd + col) = make_float2(vx, vy);
                }
            }
        }
}

// k_edge: e = ef@W3^T + A[src] + B'[dst]; write e; red into agg; deg atomics
__global__ void __launch_bounds__(256, 1)
k_edge(const float* __restrict__ ef, const int* __restrict__ src,
       const int* __restrict__ dst, float* __restrict__ e_out, int E) {
    extern __shared__ char smem[];
    uint32_t sb = smem_u32(smem);
    int tid = threadIdx.x, lane = tid & 31, warp = tid >> 5;
    int warpm = warp & 3, warpn = warp >> 2;
    int mbase = blockIdx.x * 128;                 // E % 128 == 0
    int* s_src = reinterpret_cast<int*>(smem + IDX_OFF);
    int* s_dst = s_src + 128;

    fill_A(smem, ef, mbase, 128, nullptr, tid);
    fill_B(smem, g_We_hi, g_We_lo, 256, 384, tid);
    if (tid < 128) {
        s_src[tid] = src[mbase + tid];
        s_dst[tid] = dst[mbase + tid];
    }
    __syncthreads();

    float acc[2][8][4];
    #pragma unroll
    for (int i = 0; i < 2; ++i)
        #pragma unroll
        for (int j = 0; j < 8; ++j)
            #pragma unroll
            for (int k = 0; k < 4; ++k) acc[i][j][k] = 0.f;
    run_mma(sb, lane, warpm, warpn, acc);

    int q = lane & 3, r4 = lane >> 2;
    #pragma unroll
    for (int mt = 0; mt < 2; ++mt)
        #pragma unroll
        for (int rh = 0; rh < 2; ++rh) {
            int rl = warpm * 32 + mt * 16 + rh * 8 + r4;
            int m = mbase + rl;
            int s = s_src[rl], d2 = s_dst[rl];
            const float* pA = g_AB + (size_t)s * 256;
            const float* pB = g_AB + (size_t)d2 * 256 + 128;
            float* pe = e_out + (size_t)m * D;
            float* pg = g_agg + (size_t)d2 * D;
            #pragma unroll
            for (int nt = 0; nt < 8; ++nt) {
                int col = warpn * 64 + nt * 8 + q * 2;
                float2 av = *reinterpret_cast<const float2*>(pA + col);
                float2 bv = *reinterpret_cast<const float2*>(pB + col);
                float vx = acc[mt][nt][rh * 2 + 0] + av.x + bv.x;
                float vy = acc[mt][nt][rh * 2 + 1] + av.y + bv.y;
                *reinterpret_cast<float2*>(pe + col) = make_float2(vx, vy);
                asm volatile("red.global.add.v2.f32 [%0], {%1,%2};"
                             :: "l"(pg + col), "f"(vx), "f"(vy) : "memory");
            }
            if (q == 0 && warpn == 0) atomicAdd(&g_deg[d2], 1.0f);
        }
}

// k_node: n = nf@Wn1^T + (agg/deg)@Wn2^T + b_n (two stages, register acc)
__global__ void __launch_bounds__(256, 1)
k_node(const float* __restrict__ nf, const float* __restrict__ b_n,
       float* __restrict__ n_out, int N) {
    extern __shared__ char smem[];
    uint32_t sb = smem_u32(smem);
    int tid = threadIdx.x, lane = tid & 31, warp = tid >> 5;
    int warpm = warp & 3, warpn = warp >> 2;
    int mbase = blockIdx.x * 128;
    int nrows = min(128, N - mbase);

    float acc[2][8][4];
    #pragma unroll
    for (int i = 0; i < 2; ++i)
        #pragma unroll
        for (int j = 0; j < 8; ++j)
            #pragma unroll
            for (int k = 0; k < 4; ++k) acc[i][j][k] = 0.f;

    fill_A(smem, nf, mbase, nrows, nullptr, tid);
    fill_B(smem, g_Wn_hi, g_Wn_lo, 0, 256, tid);
    __syncthreads();
    run_mma(sb, lane, warpm, warpn, acc);
    __syncthreads();

    fill_A(smem, g_agg, mbase, nrows, g_deg, tid);
    fill_B(smem, g_Wn_hi, g_Wn_lo, 128, 256, tid);
    __syncthreads();
    run_mma(sb, lane, warpm, warpn, acc);

    int q = lane & 3, r4 = lane >> 2;
    #pragma unroll
    for (int mt = 0; mt < 2; ++mt)
        #pragma unroll
        for (int rh = 0; rh < 2; ++rh) {
            int rl = warpm * 32 + mt * 16 + rh * 8 + r4;
            int m = mbase + rl;
            if (m < N) {
                float* pd = n_out + (size_t)m * D;
                #pragma unroll
                for (int nt = 0; nt < 8; ++nt) {
                    int col = warpn * 64 + nt * 8 + q * 2;
                    float2 bb = *reinterpret_cast<const float2*>(b_n + col);
                    *reinterpret_cast<float2*>(pd + col) =
                        make_float2(acc[mt][nt][rh * 2 + 0] + bb.x,
                                    acc[mt][nt][rh * 2 + 1] + bb.y);
                }
            }
        }
}

// ---------------------------------------------------------------------------
extern "C" void kernel_launch(void* const* d_in, const int* in_sizes, int n_in,
                              void* d_out, int out_size) {
    const float* nf  = (const float*)d_in[0];
    const float* ef  = (const float*)d_in[1];
    const int*   src = (const int*)d_in[2];   // int32 (JAX x64 disabled)
    const int*   dst = (const int*)d_in[3];
    const float* We  = (const float*)d_in[4];
    const float* be  = (const float*)d_in[5];
    const float* Wn  = (const float*)d_in[6];
    const float* bn  = (const float*)d_in[7];

    int N = in_sizes[0] / D;
    int E = in_sizes[1] / D;

    float* n_out = (float*)d_out;
    float* e_out = n_out + (size_t)N * D;

    cudaFuncSetAttribute(k_pre,  cudaFuncAttributeMaxDynamicSharedMemorySize, SMEM_BYTES);
    cudaFuncSetAttribute(k_edge, cudaFuncAttributeMaxDynamicSharedMemorySize, SMEM_BYTES);
    cudaFuncSetAttribute(k_node, cudaFuncAttributeMaxDynamicSharedMemorySize, SMEM_BYTES);

    int zthreads = N * (D / 4);
    k_zero<<<(zthreads + 255) / 256, 256>>>(N);
    k_wprep<<<(128 * 384 + 255) / 256, 256>>>(We, Wn);

    dim3 gpre((N + 127) / 128, 2);
    k_pre<<<gpre, 256, SMEM_BYTES>>>(nf, be, N);
    k_edge<<<E / 128, 256, SMEM_BYTES>>>(ef, src, dst, e_out, E);
    k_node<<<(N + 127) / 128, 256, SMEM_BYTES>>>(nf, bn, n_out, N);
}